// round 15
// baseline (speedup 1.0000x reference)
#include <cuda_runtime.h>
#include <cuda_fp16.h>
#include <cstdint>

// Problem constants
#define LNUM 2
#define BB   128
#define CIN  64
#define EE   64
#define NHH  8
#define MEM  40
#define HD   8
#define THD  512         // HD*HW
#define PIX  64          // spatial size
#define C_MAIN 192       // CIN + 2E
#define C_PROJ 128       // CIN + E
#define CO_MAIN 320      // 5E
#define CO_PROJ 192      // 3E

// ---- warp-MMA GEMM config ----
#define NCHUNK 54               // 9 taps * 6 channel-blocks of 32
#define ASTR 40                 // padded fp16 row stride
#define TILE_ELEMS (128 * ASTR) // 5120 fp16 per tile
#define TILE_BYTES (TILE_ELEMS * 2)  // 10240 B
#define MMA_SMEM (4 * TILE_BYTES)    // 40960 B (2 bufs x {A,B})

// ---------------- scratch (device globals; no allocation) ----------------
__device__ unsigned g_bpk [BB * (C_MAIN / 2) * PIX]; // fp16 channel-pair packed
__device__ float g_gates[BB * CO_MAIN * PIX];   // (B,320,64)
__device__ float g_kqv  [BB * CO_PROJ * PIX];   // (B,192,64)
__device__ float g_attn [BB * EE * PIX];        // (B,64,64)
__device__ float g_ao   [BB * EE * PIX];        // out-conv + residual
__device__ float g_out  [BB * EE * PIX];        // (B,64,64)
__device__ float g_bias [BB * MEM];
__device__ float g_nd   [BB];
__device__ int   g_is_i32;
// fp16 weight tiles, plain [128 r][32 k]: [layer][mtile][chunk]
__device__ __half g_wA[2 * 4 * NCHUNK * 4096];

__device__ __forceinline__ float sigmoidf_(float v) {
    return 1.0f / (1.0f + __expf(-v));
}

__device__ __forceinline__ uint32_t smem_to_u32(const void* p) {
    uint32_t a;
    asm("{ .reg .u64 t; cvta.to.shared.u64 t, %1; cvt.u32.u64 %0, t; }"
        : "=r"(a) : "l"(p));
    return a;
}
__device__ __forceinline__ void ldsm4(uint32_t addr, uint32_t* r) {
    asm volatile("ldmatrix.sync.aligned.m8n8.x4.shared.b16 {%0,%1,%2,%3}, [%4];"
        : "=r"(r[0]), "=r"(r[1]), "=r"(r[2]), "=r"(r[3]) : "r"(addr));
}
__device__ __forceinline__ void mma16816(float* d, const uint32_t* a,
                                         uint32_t b0, uint32_t b1) {
    asm volatile(
        "mma.sync.aligned.m16n8k16.row.col.f32.f16.f16.f32 "
        "{%0,%1,%2,%3}, {%4,%5,%6,%7}, {%8,%9}, {%0,%1,%2,%3};"
        : "+f"(d[0]), "+f"(d[1]), "+f"(d[2]), "+f"(d[3])
        : "r"(a[0]), "r"(a[1]), "r"(a[2]), "r"(a[3]), "r"(b0), "r"(b1));
}
__device__ __forceinline__ void cpasync16(uint32_t dst, const void* src) {
    asm volatile("cp.async.cg.shared.global [%0], [%1], 16;"
                 :: "r"(dst), "l"(src) : "memory");
}
__device__ __forceinline__ void cpasync_commit() {
    asm volatile("cp.async.commit_group;" ::: "memory");
}
__device__ __forceinline__ void cpasync_wait0() {
    asm volatile("cp.async.wait_group 0;" ::: "memory");
}

// ---------------- dtype detection for bool inputs (parallel) ----------------
__global__ void detect_kernel(const int* __restrict__ sm) {
    __shared__ int bad;
    if (threadIdx.x == 0) bad = 0;
    __syncthreads();
    int anybad = 0;
    for (int i = threadIdx.x; i < (BB * MEM) / 4; i += 256) {
        int v = sm[i];
        if (v != 0 && v != 1) anybad = 1;
    }
    if (anybad) bad = 1;
    __syncthreads();
    if (threadIdx.x == 0) g_is_i32 = !bad;
}

__device__ __forceinline__ int read_bool(const void* p, int idx) {
    if (g_is_i32) return ((const int*)p)[idx] != 0;
    return ((const unsigned char*)p)[idx] != 0;
}

// ---------------- bias + notdone ----------------
__global__ void bias_kernel(const void* __restrict__ src_mask,
                            const void* __restrict__ notdone) {
    int t = blockIdx.x * 256 + threadIdx.x;
    if (t < BB) g_nd[t] = read_bool(notdone, t) ? 1.0f : 0.0f;
    if (t >= BB * MEM) return;
    int b = t / MEM, m = t - b * MEM;
    float v;
    if (m == MEM - 1) {
        v = 3.0f;  // MASK_B
    } else {
        bool masked = read_bool(src_mask, b * MEM + m + 1) || !read_bool(notdone, b);
        v = masked ? -1e9f : 0.0f;
    }
    g_bias[t] = v;
}

// ---------------- weight prepass: fp16 tiles [128 x 32] -------------------
__global__ void wprep_kernel(const float* __restrict__ main_w,
                             const float* __restrict__ proj_w) {
    int id = blockIdx.x;
    int n = id / (4 * NCHUNK);
    int r2 = id % (4 * NCHUNK);
    int mtile = r2 / NCHUNK;
    int chunk = r2 % NCHUNK;
    int t  = chunk / 6;
    int c0 = (chunk % 6) * 32;
    __half* dh = g_wA + (size_t)id * 4096;
    for (int e = threadIdx.x; e < 4096; e += 256) {
        int r = e >> 5, kk = e & 31;
        int c = c0 + kk;
        int gco = mtile * 128 + r;
        float w = 0.0f;
        if (gco < CO_MAIN) {
            w = main_w[(((size_t)n * CO_MAIN + gco) * C_MAIN + c) * 9 + t];
        } else if (c < C_PROJ) {
            w = proj_w[(((size_t)n * CO_PROJ + (gco - CO_MAIN)) * C_PROJ + c) * 9 + t];
        }
        dh[e] = __float2half_rn(w);
    }
}

// ---------------- build concat input, fp16 channel-pair packed -----------
__global__ void prep_kernel(const float* __restrict__ x,
                            const float* __restrict__ h0,
                            int n, int first) {
    int idx = blockIdx.x * 256 + threadIdx.x;
    if (idx >= BB * (C_MAIN / 2) * PIX) return;
    int b = idx / ((C_MAIN / 2) * PIX);
    int r = idx - b * ((C_MAIN / 2) * PIX);
    int cp = r >> 6;
    int p = r & 63;
    float nd = g_nd[b];
    float vv[2];
#pragma unroll
    for (int s = 0; s < 2; s++) {
        int c = 2 * cp + s;
        float v;
        if (c < CIN) {
            v = x[b * (CIN * PIX) + c * PIX + p];
        } else if (c < CIN + EE) {
            if (first)
                v = h0[((size_t)(LNUM - 1) * BB + b) * (EE * PIX) + (c - CIN) * PIX + p] * nd;
            else
                v = g_out[(size_t)b * (EE * PIX) + (c - CIN) * PIX + p];
        } else {
            v = h0[((size_t)n * BB + b) * (EE * PIX) + (c - CIN - EE) * PIX + p] * nd;
        }
        vv[s] = v;
    }
    __half2 hp = make_half2(__float2half_rn(vv[0]), __float2half_rn(vv[1]));
    g_bpk[idx] = *(unsigned*)&hp;
}

// ---------------- warp-MMA fused conv GEMM (plain fp16) ------------------
__global__ void __launch_bounds__(256, 2)
conv_mma_kernel(const float* __restrict__ main_b,
                const float* __restrict__ proj_b,
                int n) {
    extern __shared__ __half smb[];
    uint32_t smb_u = smem_to_u32(smb);

    int tid = threadIdx.x;
    int lane = tid & 31, w = tid >> 5;
    int ntile = blockIdx.x, mtile = blockIdx.y;
    int b0 = ntile * 2;
    int mrow0 = (w >> 1) * 32;
    int nc0 = (w & 1) * 64;

    float acc[2][8][4];
#pragma unroll
    for (int mi = 0; mi < 2; mi++)
#pragma unroll
        for (int ni = 0; ni < 8; ni++)
#pragma unroll
            for (int j = 0; j < 4; j++) acc[mi][ni][j] = 0.0f;

    int lr = lane & 15, lc = lane >> 4;
    uint32_t aoff = (uint32_t)(((mrow0 + lr) * ASTR + lc * 8) * 2);
    uint32_t boff = (uint32_t)(((nc0 + lr) * ASTR + lc * 8) * 2);

    int brow = tid >> 1, half = tid & 1;
    int bb = brow >> 6, px = brow & 63;
    int yy = px >> 3, xx = px & 7;

    unsigned regB[8];

    auto loadB = [&](int chunk) {
        int t = chunk / 6;
        int cp0 = (chunk % 6) * 16;
        int ty = t / 3, tx = t % 3;
        int iy = yy + ty - 1, ix = xx + tx - 1;
        bool valid = ((unsigned)iy < 8u) && ((unsigned)ix < 8u);
        const unsigned* src = g_bpk
            + ((size_t)(b0 + bb) * (C_MAIN / 2) + cp0 + half * 8) * PIX
            + (valid ? iy * 8 + ix : 0);
#pragma unroll
        for (int j = 0; j < 8; j++)
            regB[j] = valid ? src[j * PIX] : 0u;
    };
    auto issueA = [&](int chunk, int buf) {
        size_t toff = (((size_t)n * 4 + mtile) * NCHUNK + chunk) * 4096;
        const char* gh = (const char*)(g_wA + toff);
        uint32_t base = smb_u + (uint32_t)buf * 2 * TILE_BYTES;
        {
            int e = tid;
            int row = e >> 2, c16 = e & 3;
            cpasync16(base + row * (ASTR * 2) + c16 * 16, gh + e * 16);
            e = tid + 256;
            row = e >> 2; c16 = e & 3;
            cpasync16(base + row * (ASTR * 2) + c16 * 16, gh + e * 16);
        }
        cpasync_commit();
    };
    auto storeB = [&](int buf) {
        __half* base = smb + (size_t)buf * 2 * TILE_ELEMS;
        unsigned* bh = (unsigned*)(base + TILE_ELEMS) + brow * (ASTR / 2) + half * 8;
#pragma unroll
        for (int j = 0; j < 8; j++) bh[j] = regB[j];
    };

    issueA(0, 0);
    loadB(0);
    storeB(0);
    cpasync_wait0();
    __syncthreads();

    for (int chunk = 0; chunk < NCHUNK; chunk++) {
        int buf = chunk & 1;
        if (chunk + 1 < NCHUNK) {
            issueA(chunk + 1, 1 - buf);
            loadB(chunk + 1);
        }

        uint32_t pbase = smb_u + (uint32_t)buf * 2 * TILE_BYTES;
        uint32_t pA = pbase, pB = pbase + TILE_BYTES;
#pragma unroll
        for (int ks = 0; ks < 2; ks++) {
            uint32_t kb = (uint32_t)(ks * 32);
            uint32_t ah[2][4], bh[4][4];
            ldsm4(pA + aoff + kb, ah[0]);
            ldsm4(pA + aoff + 16 * ASTR * 2 + kb, ah[1]);
#pragma unroll
            for (int pn = 0; pn < 4; pn++)
                ldsm4(pB + boff + pn * 16 * ASTR * 2 + kb, bh[pn]);
#pragma unroll
            for (int mi = 0; mi < 2; mi++) {
#pragma unroll
                for (int ni = 0; ni < 8; ni++) {
                    int pn = ni >> 1, o = ni & 1;
                    mma16816(acc[mi][ni], ah[mi], bh[pn][o], bh[pn][o + 2]);
                }
            }
        }
        if (chunk + 1 < NCHUNK) {
            storeB(1 - buf);
            cpasync_wait0();
            __syncthreads();
        }
    }

    int batch = b0 + (w & 1);
#pragma unroll
    for (int mi = 0; mi < 2; mi++) {
#pragma unroll
        for (int rr = 0; rr < 2; rr++) {
            int r = mrow0 + mi * 16 + rr * 8 + (lane >> 2);
            int gr = mtile * 128 + r;
            bool ismain = (gr < CO_MAIN);
            float bias = ismain ? main_b[n * CO_MAIN + gr]
                                : proj_b[n * CO_PROJ + (gr - CO_MAIN)];
            float* dst = ismain
                ? g_gates + ((size_t)batch * CO_MAIN + gr) * PIX
                : g_kqv  + ((size_t)batch * CO_PROJ + (gr - CO_MAIN)) * PIX;
#pragma unroll
            for (int ni = 0; ni < 8; ni++) {
                int pxc = ni * 8 + (lane & 3) * 2;
                float2 v;
                v.x = acc[mi][ni][rr * 2 + 0] + bias;
                v.y = acc[mi][ni][rr * 2 + 1] + bias;
                *(float2*)&dst[pxc] = v;
            }
        }
    }
}

// ---------------- attention over rolling memory (vectorized) -------------
__global__ void attn_kernel(const float* __restrict__ k0,
                            const float* __restrict__ v0,
                            const float* __restrict__ pos_w,
                            const float* __restrict__ pos_b,
                            int n) {
    int b = blockIdx.x;
    int h = blockIdx.y;
    int tid = threadIdx.x;
    __shared__ float q[THD], kn[THD], vn[THD];
    __shared__ float sc[MEM], wts[MEM];

    const float* kqv = g_kqv + (size_t)b * CO_PROJ * PIX;
    const float rscale = 0.044194173824159216f;  // 1/sqrt(512)
    for (int d = tid; d < THD; d += 256) {
        int hd = d >> 6, hw = d & 63;
        kn[d] = kqv[(h * 24 + hd) * PIX + hw];
        q[d]  = kqv[(h * 24 + 8 + hd) * PIX + hw] * rscale;
        vn[d] = kqv[(h * 24 + 16 + hd) * PIX + hw];
    }
    __syncthreads();

    const float* kb  = k0 + ((((size_t)n * BB + b) * NHH + h) * MEM) * THD;
    const float* pwb = pos_w + (size_t)n * MEM * (NHH * THD) + h * THD;
    int warp = tid >> 5, lane = tid & 31;

    // phase 1: scores, float4 loads, warp per m
    for (int m = warp; m < MEM; m += 8) {
        const float* kr = (m < MEM - 1) ? (kb + (size_t)(m + 1) * THD) : kn;
        const float* pr = pwb + (size_t)m * (NHH * THD);
        float p = 0.0f;
#pragma unroll
        for (int i = 0; i < 4; i++) {
            int d = lane * 4 + i * 128;
            float4 k4 = *(const float4*)(kr + d);
            float4 p4 = *(const float4*)(pr + d);
            float4 q4 = *(const float4*)(q + d);
            p += q4.x * (k4.x + p4.x) + q4.y * (k4.y + p4.y)
               + q4.z * (k4.z + p4.z) + q4.w * (k4.w + p4.w);
        }
#pragma unroll
        for (int o = 16; o; o >>= 1) p += __shfl_xor_sync(0xffffffffu, p, o);
        if (lane == 0)
            sc[m] = p + g_bias[b * MEM + m] + pos_b[(size_t)n * MEM * NHH + m * NHH + h];
    }
    __syncthreads();
    if (tid == 0) {
        float mx = sc[0];
#pragma unroll
        for (int m = 1; m < MEM; m++) mx = fmaxf(mx, sc[m]);
        float s = 0.0f;
#pragma unroll
        for (int m = 0; m < MEM; m++) {
            float e = __expf(sc[m] - mx);
            wts[m] = e;
            s += e;
        }
        float inv = 1.0f / s;
#pragma unroll
        for (int m = 0; m < MEM; m++) wts[m] *= inv;
    }
    __syncthreads();

    // phase 2: weighted V sum; 2 threads per float4 chunk (even/odd m)
    const float* vb = v0 + ((((size_t)n * BB + b) * NHH + h) * MEM) * THD;
    int t2 = tid >> 1, par = tid & 1;    // t2 in 0..127
    int d = t2 * 4;
    float4 acc = make_float4(0.0f, 0.0f, 0.0f, 0.0f);
    for (int m = par; m < MEM - 1; m += 2) {
        float4 v4 = *(const float4*)(vb + (size_t)(m + 1) * THD + d);
        float wv = wts[m];
        acc.x = fmaf(wv, v4.x, acc.x);
        acc.y = fmaf(wv, v4.y, acc.y);
        acc.z = fmaf(wv, v4.z, acc.z);
        acc.w = fmaf(wv, v4.w, acc.w);
    }
    if (par == 1) {
        float4 v4 = *(const float4*)(vn + d);
        float wv = wts[MEM - 1];
        acc.x = fmaf(wv, v4.x, acc.x);
        acc.y = fmaf(wv, v4.y, acc.y);
        acc.z = fmaf(wv, v4.z, acc.z);
        acc.w = fmaf(wv, v4.w, acc.w);
    }
    acc.x += __shfl_xor_sync(0xffffffffu, acc.x, 1);
    acc.y += __shfl_xor_sync(0xffffffffu, acc.y, 1);
    acc.z += __shfl_xor_sync(0xffffffffu, acc.z, 1);
    acc.w += __shfl_xor_sync(0xffffffffu, acc.w, 1);
    if (par == 0)
        *(float4*)(g_attn + (size_t)b * (EE * PIX) + h * THD + d) = acc;
}

// ---------------- out conv + residual (parallel over 4 co-groups) --------
__global__ void __launch_bounds__(128, 8)
final_conv_kernel(const float* __restrict__ out_w,
                  const float* __restrict__ out_b,
                  const float* __restrict__ x,
                  int n) {
    __shared__ float sa[EE * 100];   // padded attn input
    int b = blockIdx.x;
    int g = blockIdx.y;              // co group: [g*16, g*16+16)
    int tid = threadIdx.x;           // 128

    for (int i = tid; i < EE * 100; i += 128) sa[i] = 0.0f;
    __syncthreads();
    const float* at = g_attn + (size_t)b * EE * PIX;
    for (int i = tid; i < EE * PIX; i += 128) {
        int c = i >> 6, p = i & 63;
        sa[c * 100 + ((p >> 3) + 1) * 10 + (p & 7) + 1] = at[i];
    }
    __syncthreads();

    int co = g * 16 + (tid >> 3);
    int row = tid & 7;
    const float* wc = out_w + ((size_t)n * EE + co) * EE * 9;
    float acc[8];
#pragma unroll
    for (int xx = 0; xx < 8; xx++) acc[xx] = 0.0f;
    for (int c = 0; c < EE; c++) {
        const float* s = sa + c * 100 + row * 10;
        const float* w = wc + c * 9;
        float w0 = w[0], w1 = w[1], w2 = w[2];
        float w3 = w[3], w4 = w[4], w5 = w[5];
        float w6 = w[6], w7 = w[7], w8 = w[8];
#pragma unroll
        for (int xx = 0; xx < 8; xx++) {
            float a = acc[xx];
            a = fmaf(s[xx],      w0, a);
            a = fmaf(s[xx + 1],  w1, a);
            a = fmaf(s[xx + 2],  w2, a);
            a = fmaf(s[10 + xx],     w3, a);
            a = fmaf(s[10 + xx + 1], w4, a);
            a = fmaf(s[10 + xx + 2], w5, a);
            a = fmaf(s[20 + xx],     w6, a);
            a = fmaf(s[20 + xx + 1], w7, a);
            a = fmaf(s[20 + xx + 2], w8, a);
            acc[xx] = a;
        }
    }
    float bb = out_b[n * EE + co];
    const float* xr = x + (size_t)b * EE * PIX;
    float* dst = g_ao + (size_t)b * EE * PIX + co * PIX + row * 8;
    int base = co * PIX + row * 8;
#pragma unroll
    for (int xx = 0; xx < 8; xx++)
        dst[xx] = acc[xx] + bb + xr[base + xx];
}

// ---------------- layernorm + LSTM combine ----------------
__global__ void final_ln_kernel(const float* __restrict__ ln_w,
                                const float* __restrict__ ln_b,
                                const float* __restrict__ c0,
                                int n, float* __restrict__ dst_last, int last) {
    __shared__ float red[16];
    __shared__ float s_mu, s_rv;
    int b = blockIdx.x;
    int tid = threadIdx.x;

    const float* aop = g_ao + (size_t)b * EE * PIX;
    float v16[16];
    float s1 = 0.0f, s2 = 0.0f;
#pragma unroll
    for (int j = 0; j < 16; j++) {
        float v = aop[tid + 256 * j];
        v16[j] = v;
        s1 += v;
        s2 += v * v;
    }
    int warp = tid >> 5, lane = tid & 31;
#pragma unroll
    for (int o = 16; o; o >>= 1) {
        s1 += __shfl_xor_sync(0xffffffffu, s1, o);
        s2 += __shfl_xor_sync(0xffffffffu, s2, o);
    }
    if (lane == 0) { red[warp] = s1; red[8 + warp] = s2; }
    __syncthreads();
    if (tid == 0) {
        float a = 0.0f, q2 = 0.0f;
#pragma unroll
        for (int w2 = 0; w2 < 8; w2++) { a += red[w2]; q2 += red[8 + w2]; }
        float mu = a * (1.0f / 4096.0f);
        float var = q2 * (1.0f / 4096.0f) - mu * mu;
        s_mu = mu;
        s_rv = rsqrtf(var + 1e-5f);
    }
    __syncthreads();
    float mu = s_mu, rv = s_rv;

    const float* gb = g_gates + (size_t)b * CO_MAIN * PIX;
    const float* cb = c0 + ((size_t)n * BB + b) * (EE * PIX);
    float nd = g_nd[b];
    float* dst = (last ? dst_last : g_out) + (size_t)b * EE * PIX;
    const float* lw = ln_w + (size_t)n * EE * PIX;
    const float* lb = ln_b + (size_t)n * EE * PIX;
#pragma unroll
    for (int j = 0; j < 16; j++) {
        int i = tid + 256 * j;
        int c = i >> 6, p = i & 63;
        float aon = (v16[j] - mu) * rv * lw[i] + lb[i];
        float gi = sigmoidf_(gb[(0 * EE + c) * PIX + p]);
        float gf = sigmoidf_(gb[(1 * EE + c) * PIX + p]);
        float go = sigmoidf_(gb[(2 * EE + c) * PIX + p]);
        float gg = tanhf(gb[(3 * EE + c) * PIX + p]);
        float ga = sigmoidf_(gb[(4 * EE + c) * PIX + p]);
        float cn = gf * (cb[i] * nd) + gi * gg + ga * tanhf(aon);
        dst[i] = go * tanhf(cn);
    }
}

// ---------------- launch ----------------
extern "C" void kernel_launch(void* const* d_in, const int* in_sizes, int n_in,
                              void* d_out, int out_size) {
    const float* x       = (const float*)d_in[0];
    const float* h0      = (const float*)d_in[1];
    const float* c0      = (const float*)d_in[2];
    const float* k0      = (const float*)d_in[3];
    const float* v0      = (const float*)d_in[4];
    const void*  src_mask = d_in[5];
    const void*  notdone  = d_in[6];
    const float* main_w  = (const float*)d_in[7];
    const float* main_b  = (const float*)d_in[8];
    const float* proj_w  = (const float*)d_in[9];
    const float* proj_b  = (const float*)d_in[10];
    const float* out_w   = (const float*)d_in[11];
    const float* out_b   = (const float*)d_in[12];
    const float* ln_w    = (const float*)d_in[13];
    const float* ln_b    = (const float*)d_in[14];
    const float* pos_w   = (const float*)d_in[15];
    const float* pos_b   = (const float*)d_in[16];
    float* out = (float*)d_out;

    cudaFuncSetAttribute(conv_mma_kernel,
                         cudaFuncAttributeMaxDynamicSharedMemorySize, MMA_SMEM);

    detect_kernel<<<1, 256>>>((const int*)src_mask);
    bias_kernel<<<(BB * MEM + 255) / 256, 256>>>(src_mask, notdone);
    wprep_kernel<<<2 * 4 * NCHUNK, 256>>>(main_w, proj_w);
    for (int n = 0; n < LNUM; n++) {
        int tot = BB * (C_MAIN / 2) * PIX;
        prep_kernel<<<(tot + 255) / 256, 256>>>(x, h0, n, n == 0 ? 1 : 0);
        conv_mma_kernel<<<dim3(64, 4), 256, MMA_SMEM>>>(main_b, proj_b, n);
        attn_kernel<<<dim3(BB, NHH), 256>>>(k0, v0, pos_w, pos_b, n);
        final_conv_kernel<<<dim3(BB, 4), 128>>>(out_w, out_b, x, n);
        final_ln_kernel<<<BB, 256>>>(ln_w, ln_b, c0, n,
                                     out, n == LNUM - 1 ? 1 : 0);
    }
}

// round 16
// speedup vs baseline: 1.1480x; 1.1480x over previous
#include <cuda_runtime.h>
#include <cuda_fp16.h>
#include <cstdint>

// Problem constants
#define LNUM 2
#define BB   128
#define CIN  64
#define EE   64
#define NHH  8
#define MEM  40
#define HD   8
#define THD  512         // HD*HW
#define PIX  64          // spatial size
#define C_MAIN 192       // CIN + 2E
#define C_PROJ 128       // CIN + E
#define CO_MAIN 320      // 5E
#define CO_PROJ 192      // 3E

// ---- warp-MMA GEMM config (main fused conv) ----
#define NCHUNK 54               // 9 taps * 6 channel-blocks of 32
#define ASTR 40                 // padded fp16 row stride
#define TILE_ELEMS (128 * ASTR) // 5120 fp16 per tile
#define TILE_BYTES (TILE_ELEMS * 2)  // 10240 B
#define MMA_SMEM (4 * TILE_BYTES)    // 40960 B (2 bufs x {A,B})

// ---- out-conv MMA config ----
#define OCHUNK 18               // 9 taps * 2 channel-blocks of 32
#define OA_ELEMS (64 * ASTR)    // A tile 64 x ASTR
#define OB_ELEMS (128 * ASTR)   // B tile 128 x ASTR
#define OBUF_ELEMS (OA_ELEMS + OB_ELEMS)
#define OC_SMEM (2 * OBUF_ELEMS * 2)  // 30720 B

// ---------------- scratch (device globals; no allocation) ----------------
__device__ unsigned g_bpk [BB * (C_MAIN / 2) * PIX]; // fp16 channel-pair packed
__device__ float g_gates[BB * CO_MAIN * PIX];   // (B,320,64)
__device__ float g_kqv  [BB * CO_PROJ * PIX];   // (B,192,64)
__device__ float g_attn [BB * EE * PIX];        // (B,64,64)
__device__ float g_ao   [BB * EE * PIX];        // out-conv + residual
__device__ float g_out  [BB * EE * PIX];        // (B,64,64)
__device__ float g_bias [BB * MEM];
__device__ float g_nd   [BB];
__device__ int   g_is_i32;
// fp16 weight tiles: main conv [layer][mtile][chunk][128x32], out conv [layer][chunk][64x32]
__device__ __half g_wA[2 * 4 * NCHUNK * 4096];
__device__ __half g_wO[2 * OCHUNK * 2048];

__device__ __forceinline__ float sigmoidf_(float v) {
    return 1.0f / (1.0f + __expf(-v));
}

__device__ __forceinline__ uint32_t smem_to_u32(const void* p) {
    uint32_t a;
    asm("{ .reg .u64 t; cvta.to.shared.u64 t, %1; cvt.u32.u64 %0, t; }"
        : "=r"(a) : "l"(p));
    return a;
}
__device__ __forceinline__ void ldsm4(uint32_t addr, uint32_t* r) {
    asm volatile("ldmatrix.sync.aligned.m8n8.x4.shared.b16 {%0,%1,%2,%3}, [%4];"
        : "=r"(r[0]), "=r"(r[1]), "=r"(r[2]), "=r"(r[3]) : "r"(addr));
}
__device__ __forceinline__ void mma16816(float* d, const uint32_t* a,
                                         uint32_t b0, uint32_t b1) {
    asm volatile(
        "mma.sync.aligned.m16n8k16.row.col.f32.f16.f16.f32 "
        "{%0,%1,%2,%3}, {%4,%5,%6,%7}, {%8,%9}, {%0,%1,%2,%3};"
        : "+f"(d[0]), "+f"(d[1]), "+f"(d[2]), "+f"(d[3])
        : "r"(a[0]), "r"(a[1]), "r"(a[2]), "r"(a[3]), "r"(b0), "r"(b1));
}
__device__ __forceinline__ void cpasync16(uint32_t dst, const void* src) {
    asm volatile("cp.async.cg.shared.global [%0], [%1], 16;"
                 :: "r"(dst), "l"(src) : "memory");
}
__device__ __forceinline__ void cpasync_commit() {
    asm volatile("cp.async.commit_group;" ::: "memory");
}
__device__ __forceinline__ void cpasync_wait0() {
    asm volatile("cp.async.wait_group 0;" ::: "memory");
}

// ---------------- dtype detection for bool inputs (parallel) ----------------
__global__ void detect_kernel(const int* __restrict__ sm) {
    __shared__ int bad;
    if (threadIdx.x == 0) bad = 0;
    __syncthreads();
    int anybad = 0;
    for (int i = threadIdx.x; i < (BB * MEM) / 4; i += 256) {
        int v = sm[i];
        if (v != 0 && v != 1) anybad = 1;
    }
    if (anybad) bad = 1;
    __syncthreads();
    if (threadIdx.x == 0) g_is_i32 = !bad;
}

__device__ __forceinline__ int read_bool(const void* p, int idx) {
    if (g_is_i32) return ((const int*)p)[idx] != 0;
    return ((const unsigned char*)p)[idx] != 0;
}

// ---------------- bias + notdone ----------------
__global__ void bias_kernel(const void* __restrict__ src_mask,
                            const void* __restrict__ notdone) {
    int t = blockIdx.x * 256 + threadIdx.x;
    if (t < BB) g_nd[t] = read_bool(notdone, t) ? 1.0f : 0.0f;
    if (t >= BB * MEM) return;
    int b = t / MEM, m = t - b * MEM;
    float v;
    if (m == MEM - 1) {
        v = 3.0f;  // MASK_B
    } else {
        bool masked = read_bool(src_mask, b * MEM + m + 1) || !read_bool(notdone, b);
        v = masked ? -1e9f : 0.0f;
    }
    g_bias[t] = v;
}

// ---------------- weight prepass: main conv fp16 tiles [128 x 32] ---------
__global__ void wprep_kernel(const float* __restrict__ main_w,
                             const float* __restrict__ proj_w) {
    int id = blockIdx.x;
    int n = id / (4 * NCHUNK);
    int r2 = id % (4 * NCHUNK);
    int mtile = r2 / NCHUNK;
    int chunk = r2 % NCHUNK;
    int t  = chunk / 6;
    int c0 = (chunk % 6) * 32;
    __half* dh = g_wA + (size_t)id * 4096;
    for (int e = threadIdx.x; e < 4096; e += 256) {
        int r = e >> 5, kk = e & 31;
        int c = c0 + kk;
        int gco = mtile * 128 + r;
        float w = 0.0f;
        if (gco < CO_MAIN) {
            w = main_w[(((size_t)n * CO_MAIN + gco) * C_MAIN + c) * 9 + t];
        } else if (c < C_PROJ) {
            w = proj_w[(((size_t)n * CO_PROJ + (gco - CO_MAIN)) * C_PROJ + c) * 9 + t];
        }
        dh[e] = __float2half_rn(w);
    }
}

// ---------------- weight prepass: out conv fp16 tiles [64 x 32] -----------
__global__ void wprep2_kernel(const float* __restrict__ out_w) {
    int id = blockIdx.x;               // 2 * OCHUNK blocks
    int n = id / OCHUNK;
    int chunk = id % OCHUNK;
    int t  = chunk >> 1;
    int c0 = (chunk & 1) * 32;
    __half* dh = g_wO + (size_t)id * 2048;
    for (int e = threadIdx.x; e < 2048; e += 256) {
        int r = e >> 5, kk = e & 31;
        float w = out_w[(((size_t)n * EE + r) * EE + c0 + kk) * 9 + t];
        dh[e] = __float2half_rn(w);
    }
}

// ---------------- build concat input, fp16 channel-pair packed -----------
__global__ void prep_kernel(const float* __restrict__ x,
                            const float* __restrict__ h0,
                            int n, int first) {
    int idx = blockIdx.x * 256 + threadIdx.x;
    if (idx >= BB * (C_MAIN / 2) * PIX) return;
    int b = idx / ((C_MAIN / 2) * PIX);
    int r = idx - b * ((C_MAIN / 2) * PIX);
    int cp = r >> 6;
    int p = r & 63;
    float nd = g_nd[b];
    float vv[2];
#pragma unroll
    for (int s = 0; s < 2; s++) {
        int c = 2 * cp + s;
        float v;
        if (c < CIN) {
            v = x[b * (CIN * PIX) + c * PIX + p];
        } else if (c < CIN + EE) {
            if (first)
                v = h0[((size_t)(LNUM - 1) * BB + b) * (EE * PIX) + (c - CIN) * PIX + p] * nd;
            else
                v = g_out[(size_t)b * (EE * PIX) + (c - CIN) * PIX + p];
        } else {
            v = h0[((size_t)n * BB + b) * (EE * PIX) + (c - CIN - EE) * PIX + p] * nd;
        }
        vv[s] = v;
    }
    __half2 hp = make_half2(__float2half_rn(vv[0]), __float2half_rn(vv[1]));
    g_bpk[idx] = *(unsigned*)&hp;
}

// ---------------- warp-MMA fused conv GEMM (plain fp16) ------------------
__global__ void __launch_bounds__(256, 2)
conv_mma_kernel(const float* __restrict__ main_b,
                const float* __restrict__ proj_b,
                int n) {
    extern __shared__ __half smb[];
    uint32_t smb_u = smem_to_u32(smb);

    int tid = threadIdx.x;
    int lane = tid & 31, w = tid >> 5;
    int ntile = blockIdx.x, mtile = blockIdx.y;
    int b0 = ntile * 2;
    int mrow0 = (w >> 1) * 32;
    int nc0 = (w & 1) * 64;

    float acc[2][8][4];
#pragma unroll
    for (int mi = 0; mi < 2; mi++)
#pragma unroll
        for (int ni = 0; ni < 8; ni++)
#pragma unroll
            for (int j = 0; j < 4; j++) acc[mi][ni][j] = 0.0f;

    int lr = lane & 15, lc = lane >> 4;
    uint32_t aoff = (uint32_t)(((mrow0 + lr) * ASTR + lc * 8) * 2);
    uint32_t boff = (uint32_t)(((nc0 + lr) * ASTR + lc * 8) * 2);

    int brow = tid >> 1, half = tid & 1;
    int bb = brow >> 6, px = brow & 63;
    int yy = px >> 3, xx = px & 7;

    unsigned regB[8];

    auto loadB = [&](int chunk) {
        int t = chunk / 6;
        int cp0 = (chunk % 6) * 16;
        int ty = t / 3, tx = t % 3;
        int iy = yy + ty - 1, ix = xx + tx - 1;
        bool valid = ((unsigned)iy < 8u) && ((unsigned)ix < 8u);
        const unsigned* src = g_bpk
            + ((size_t)(b0 + bb) * (C_MAIN / 2) + cp0 + half * 8) * PIX
            + (valid ? iy * 8 + ix : 0);
#pragma unroll
        for (int j = 0; j < 8; j++)
            regB[j] = valid ? src[j * PIX] : 0u;
    };
    auto issueA = [&](int chunk, int buf) {
        size_t toff = (((size_t)n * 4 + mtile) * NCHUNK + chunk) * 4096;
        const char* gh = (const char*)(g_wA + toff);
        uint32_t base = smb_u + (uint32_t)buf * 2 * TILE_BYTES;
        {
            int e = tid;
            int row = e >> 2, c16 = e & 3;
            cpasync16(base + row * (ASTR * 2) + c16 * 16, gh + e * 16);
            e = tid + 256;
            row = e >> 2; c16 = e & 3;
            cpasync16(base + row * (ASTR * 2) + c16 * 16, gh + e * 16);
        }
        cpasync_commit();
    };
    auto storeB = [&](int buf) {
        __half* base = smb + (size_t)buf * 2 * TILE_ELEMS;
        unsigned* bh = (unsigned*)(base + TILE_ELEMS) + brow * (ASTR / 2) + half * 8;
#pragma unroll
        for (int j = 0; j < 8; j++) bh[j] = regB[j];
    };

    issueA(0, 0);
    loadB(0);
    storeB(0);
    cpasync_wait0();
    __syncthreads();

    for (int chunk = 0; chunk < NCHUNK; chunk++) {
        int buf = chunk & 1;
        if (chunk + 1 < NCHUNK) {
            issueA(chunk + 1, 1 - buf);
            loadB(chunk + 1);
        }

        uint32_t pbase = smb_u + (uint32_t)buf * 2 * TILE_BYTES;
        uint32_t pA = pbase, pB = pbase + TILE_BYTES;
#pragma unroll
        for (int ks = 0; ks < 2; ks++) {
            uint32_t kb = (uint32_t)(ks * 32);
            uint32_t ah[2][4], bh[4][4];
            ldsm4(pA + aoff + kb, ah[0]);
            ldsm4(pA + aoff + 16 * ASTR * 2 + kb, ah[1]);
#pragma unroll
            for (int pn = 0; pn < 4; pn++)
                ldsm4(pB + boff + pn * 16 * ASTR * 2 + kb, bh[pn]);
#pragma unroll
            for (int mi = 0; mi < 2; mi++) {
#pragma unroll
                for (int ni = 0; ni < 8; ni++) {
                    int pn = ni >> 1, o = ni & 1;
                    mma16816(acc[mi][ni], ah[mi], bh[pn][o], bh[pn][o + 2]);
                }
            }
        }
        if (chunk + 1 < NCHUNK) {
            storeB(1 - buf);
            cpasync_wait0();
            __syncthreads();
        }
    }

    int batch = b0 + (w & 1);
#pragma unroll
    for (int mi = 0; mi < 2; mi++) {
#pragma unroll
        for (int rr = 0; rr < 2; rr++) {
            int r = mrow0 + mi * 16 + rr * 8 + (lane >> 2);
            int gr = mtile * 128 + r;
            bool ismain = (gr < CO_MAIN);
            float bias = ismain ? main_b[n * CO_MAIN + gr]
                                : proj_b[n * CO_PROJ + (gr - CO_MAIN)];
            float* dst = ismain
                ? g_gates + ((size_t)batch * CO_MAIN + gr) * PIX
                : g_kqv  + ((size_t)batch * CO_PROJ + (gr - CO_MAIN)) * PIX;
#pragma unroll
            for (int ni = 0; ni < 8; ni++) {
                int pxc = ni * 8 + (lane & 3) * 2;
                float2 v;
                v.x = acc[mi][ni][rr * 2 + 0] + bias;
                v.y = acc[mi][ni][rr * 2 + 1] + bias;
                *(float2*)&dst[pxc] = v;
            }
        }
    }
}

// ---------------- attention over rolling memory (R14 version) ------------
__global__ void attn_kernel(const float* __restrict__ k0,
                            const float* __restrict__ v0,
                            const float* __restrict__ pos_w,
                            const float* __restrict__ pos_b,
                            int n) {
    int b = blockIdx.x;
    int h = blockIdx.y;
    int tid = threadIdx.x;
    __shared__ float q[THD], kn[THD], vn[THD];
    __shared__ float sc[MEM], wts[MEM];

    const float* kqv = g_kqv + (size_t)b * CO_PROJ * PIX;
    const float rscale = 0.044194173824159216f;  // 1/sqrt(512)
    for (int d = tid; d < THD; d += 256) {
        int hd = d >> 6, hw = d & 63;
        kn[d] = kqv[(h * 24 + hd) * PIX + hw];
        q[d]  = kqv[(h * 24 + 8 + hd) * PIX + hw] * rscale;
        vn[d] = kqv[(h * 24 + 16 + hd) * PIX + hw];
    }
    __syncthreads();

    const float* kb  = k0 + ((((size_t)n * BB + b) * NHH + h) * MEM) * THD;
    const float* pwb = pos_w + (size_t)n * MEM * (NHH * THD) + h * THD;
    int warp = tid >> 5, lane = tid & 31;
    for (int m = warp; m < MEM; m += 8) {
        const float* kr = (m < MEM - 1) ? (kb + (size_t)(m + 1) * THD) : kn;
        const float* pr = pwb + (size_t)m * (NHH * THD);
        float p = 0.0f;
        for (int d = lane; d < THD; d += 32)
            p = fmaf(q[d], kr[d] + pr[d], p);
#pragma unroll
        for (int o = 16; o; o >>= 1) p += __shfl_xor_sync(0xffffffffu, p, o);
        if (lane == 0)
            sc[m] = p + g_bias[b * MEM + m] + pos_b[(size_t)n * MEM * NHH + m * NHH + h];
    }
    __syncthreads();
    if (tid == 0) {
        float mx = sc[0];
#pragma unroll
        for (int m = 1; m < MEM; m++) mx = fmaxf(mx, sc[m]);
        float s = 0.0f;
#pragma unroll
        for (int m = 0; m < MEM; m++) {
            float e = __expf(sc[m] - mx);
            wts[m] = e;
            s += e;
        }
        float inv = 1.0f / s;
#pragma unroll
        for (int m = 0; m < MEM; m++) wts[m] *= inv;
    }
    __syncthreads();

    const float* vb = v0 + ((((size_t)n * BB + b) * NHH + h) * MEM) * THD;
    for (int d = tid; d < THD; d += 256) {
        float acc = wts[MEM - 1] * vn[d];
        for (int m = 0; m < MEM - 1; m++)
            acc = fmaf(wts[m], vb[(size_t)(m + 1) * THD + d], acc);
        int hd = d >> 6, hw = d & 63;
        g_attn[(size_t)b * (EE * PIX) + (h * 8 + hd) * PIX + hw] = acc;
    }
}

// ---------------- out conv via fp16 MMA (+bias +residual) ----------------
// GEMM: D[64 co][N] = W[64,576] x B[576,N]; K = 9 taps x 64 ch.
// grid 64 blocks (2 batches each), 256 thr = 8 warps (4m x 2n).
__global__ void __launch_bounds__(256, 2)
outconv_mma_kernel(const float* __restrict__ out_b,
                   const float* __restrict__ x,
                   int n) {
    extern __shared__ __half smb[];
    uint32_t smb_u = smem_to_u32(smb);

    int tid = threadIdx.x;
    int lane = tid & 31, w = tid >> 5;
    int b0 = blockIdx.x * 2;
    int mrow0 = (w >> 1) * 16;      // 4 m-warps x 16 rows
    int nc0 = (w & 1) * 64;

    float acc[8][4];
#pragma unroll
    for (int ni = 0; ni < 8; ni++)
#pragma unroll
        for (int j = 0; j < 4; j++) acc[ni][j] = 0.0f;

    int lr = lane & 15, lc = lane >> 4;
    uint32_t aoff = (uint32_t)(((mrow0 + lr) * ASTR + lc * 8) * 2);
    uint32_t boff = (uint32_t)(((nc0 + lr) * ASTR + lc * 8) * 2);

    // B staging: 2 threads per row (16 channels each)
    int brow = tid >> 1, half = tid & 1;
    int bb = brow >> 6, px = brow & 63;
    int yy = px >> 3, xx = px & 7;

    unsigned regB[8];

    auto loadB = [&](int chunk) {
        int t = chunk >> 1;
        int c0 = (chunk & 1) * 32 + half * 16;
        int ty = t / 3, tx = t % 3;
        int iy = yy + ty - 1, ix = xx + tx - 1;
        bool valid = ((unsigned)iy < 8u) && ((unsigned)ix < 8u);
        const float* src = g_attn + ((size_t)(b0 + bb) * EE + c0) * PIX
                                  + (valid ? iy * 8 + ix : 0);
#pragma unroll
        for (int j = 0; j < 8; j++) {
            float v0 = valid ? src[(2 * j) * PIX] : 0.0f;
            float v1 = valid ? src[(2 * j + 1) * PIX] : 0.0f;
            __half2 hp = make_half2(__float2half_rn(v0), __float2half_rn(v1));
            regB[j] = *(unsigned*)&hp;
        }
    };
    auto issueA = [&](int chunk, int buf) {
        size_t toff = ((size_t)n * OCHUNK + chunk) * 2048;
        const char* gh = (const char*)(g_wO + toff);
        uint32_t base = smb_u + (uint32_t)buf * OBUF_ELEMS * 2;
        int e = tid;                      // 256 chunks of 16B
        int row = e >> 2, c16 = e & 3;
        cpasync16(base + row * (ASTR * 2) + c16 * 16, gh + e * 16);
        cpasync_commit();
    };
    auto storeB = [&](int buf) {
        __half* base = smb + (size_t)buf * OBUF_ELEMS + OA_ELEMS;
        unsigned* bh = (unsigned*)base + brow * (ASTR / 2) + half * 8;
#pragma unroll
        for (int j = 0; j < 8; j++) bh[j] = regB[j];
    };

    issueA(0, 0);
    loadB(0);
    storeB(0);
    cpasync_wait0();
    __syncthreads();

    for (int chunk = 0; chunk < OCHUNK; chunk++) {
        int buf = chunk & 1;
        if (chunk + 1 < OCHUNK) {
            issueA(chunk + 1, 1 - buf);
            loadB(chunk + 1);
        }

        uint32_t pbase = smb_u + (uint32_t)buf * OBUF_ELEMS * 2;
        uint32_t pA = pbase, pB = pbase + OA_ELEMS * 2;
#pragma unroll
        for (int ks = 0; ks < 2; ks++) {
            uint32_t kb = (uint32_t)(ks * 32);
            uint32_t ah[4], bh[4][4];
            ldsm4(pA + aoff + kb, ah);
#pragma unroll
            for (int pn = 0; pn < 4; pn++)
                ldsm4(pB + boff + pn * 16 * ASTR * 2 + kb, bh[pn]);
#pragma unroll
            for (int ni = 0; ni < 8; ni++) {
                int pn = ni >> 1, o = ni & 1;
                mma16816(acc[ni], ah, bh[pn][o], bh[pn][o + 2]);
            }
        }
        if (chunk + 1 < OCHUNK) {
            storeB(1 - buf);
            cpasync_wait0();
            __syncthreads();
        }
    }

    // epilogue: bias + residual, write g_ao
    int batch = b0 + (w & 1);
    const float* xr = x + (size_t)batch * EE * PIX;
    float* aob = g_ao + (size_t)batch * EE * PIX;
#pragma unroll
    for (int rr = 0; rr < 2; rr++) {
        int co = mrow0 + rr * 8 + (lane >> 2);
        float bias = out_b[n * EE + co];
#pragma unroll
        for (int ni = 0; ni < 8; ni++) {
            int pxc = ni * 8 + (lane & 3) * 2;
            float2 rx = *(const float2*)&xr[co * PIX + pxc];
            float2 v;
            v.x = acc[ni][rr * 2 + 0] + bias + rx.x;
            v.y = acc[ni][rr * 2 + 1] + bias + rx.y;
            *(float2*)&aob[co * PIX + pxc] = v;
        }
    }
}

// ---------------- layernorm + LSTM combine ----------------
__global__ void final_ln_kernel(const float* __restrict__ ln_w,
                                const float* __restrict__ ln_b,
                                const float* __restrict__ c0,
                                int n, float* __restrict__ dst_last, int last) {
    __shared__ float red[16];
    __shared__ float s_mu, s_rv;
    int b = blockIdx.x;
    int tid = threadIdx.x;

    const float* aop = g_ao + (size_t)b * EE * PIX;
    float v16[16];
    float s1 = 0.0f, s2 = 0.0f;
#pragma unroll
    for (int j = 0; j < 16; j++) {
        float v = aop[tid + 256 * j];
        v16[j] = v;
        s1 += v;
        s2 += v * v;
    }
    int warp = tid >> 5, lane = tid & 31;
#pragma unroll
    for (int o = 16; o; o >>= 1) {
        s1 += __shfl_xor_sync(0xffffffffu, s1, o);
        s2 += __shfl_xor_sync(0xffffffffu, s2, o);
    }
    if (lane == 0) { red[warp] = s1; red[8 + warp] = s2; }
    __syncthreads();
    if (tid == 0) {
        float a = 0.0f, q2 = 0.0f;
#pragma unroll
        for (int w2 = 0; w2 < 8; w2++) { a += red[w2]; q2 += red[8 + w2]; }
        float mu = a * (1.0f / 4096.0f);
        float var = q2 * (1.0f / 4096.0f) - mu * mu;
        s_mu = mu;
        s_rv = rsqrtf(var + 1e-5f);
    }
    __syncthreads();
    float mu = s_mu, rv = s_rv;

    const float* gb = g_gates + (size_t)b * CO_MAIN * PIX;
    const float* cb = c0 + ((size_t)n * BB + b) * (EE * PIX);
    float nd = g_nd[b];
    float* dst = (last ? dst_last : g_out) + (size_t)b * EE * PIX;
    const float* lw = ln_w + (size_t)n * EE * PIX;
    const float* lb = ln_b + (size_t)n * EE * PIX;
#pragma unroll
    for (int j = 0; j < 16; j++) {
        int i = tid + 256 * j;
        int c = i >> 6, p = i & 63;
        float aon = (v16[j] - mu) * rv * lw[i] + lb[i];
        float gi = sigmoidf_(gb[(0 * EE + c) * PIX + p]);
        float gf = sigmoidf_(gb[(1 * EE + c) * PIX + p]);
        float go = sigmoidf_(gb[(2 * EE + c) * PIX + p]);
        float gg = tanhf(gb[(3 * EE + c) * PIX + p]);
        float ga = sigmoidf_(gb[(4 * EE + c) * PIX + p]);
        float cn = gf * (cb[i] * nd) + gi * gg + ga * tanhf(aon);
        dst[i] = go * tanhf(cn);
    }
}

// ---------------- launch ----------------
extern "C" void kernel_launch(void* const* d_in, const int* in_sizes, int n_in,
                              void* d_out, int out_size) {
    const float* x       = (const float*)d_in[0];
    const float* h0      = (const float*)d_in[1];
    const float* c0      = (const float*)d_in[2];
    const float* k0      = (const float*)d_in[3];
    const float* v0      = (const float*)d_in[4];
    const void*  src_mask = d_in[5];
    const void*  notdone  = d_in[6];
    const float* main_w  = (const float*)d_in[7];
    const float* main_b  = (const float*)d_in[8];
    const float* proj_w  = (const float*)d_in[9];
    const float* proj_b  = (const float*)d_in[10];
    const float* out_w   = (const float*)d_in[11];
    const float* out_b   = (const float*)d_in[12];
    const float* ln_w    = (const float*)d_in[13];
    const float* ln_b    = (const float*)d_in[14];
    const float* pos_w   = (const float*)d_in[15];
    const float* pos_b   = (const float*)d_in[16];
    float* out = (float*)d_out;

    cudaFuncSetAttribute(conv_mma_kernel,
                         cudaFuncAttributeMaxDynamicSharedMemorySize, MMA_SMEM);
    cudaFuncSetAttribute(outconv_mma_kernel,
                         cudaFuncAttributeMaxDynamicSharedMemorySize, OC_SMEM);

    detect_kernel<<<1, 256>>>((const int*)src_mask);
    bias_kernel<<<(BB * MEM + 255) / 256, 256>>>(src_mask, notdone);
    wprep_kernel<<<2 * 4 * NCHUNK, 256>>>(main_w, proj_w);
    wprep2_kernel<<<2 * OCHUNK, 256>>>(out_w);
    for (int n = 0; n < LNUM; n++) {
        int tot = BB * (C_MAIN / 2) * PIX;
        prep_kernel<<<(tot + 255) / 256, 256>>>(x, h0, n, n == 0 ? 1 : 0);
        conv_mma_kernel<<<dim3(64, 4), 256, MMA_SMEM>>>(main_b, proj_b, n);
        attn_kernel<<<dim3(BB, NHH), 256>>>(k0, v0, pos_w, pos_b, n);
        outconv_mma_kernel<<<64, 256, OC_SMEM>>>(out_b, x, n);
        final_ln_kernel<<<BB, 256>>>(ln_w, ln_b, c0, n,
                                     out, n == LNUM - 1 ? 1 : 0);
    }
}

// round 17
// speedup vs baseline: 1.2391x; 1.0794x over previous
#include <cuda_runtime.h>
#include <cuda_fp16.h>
#include <cstdint>

// Problem constants
#define LNUM 2
#define BB   128
#define CIN  64
#define EE   64
#define NHH  8
#define MEM  40
#define HD   8
#define THD  512         // HD*HW
#define PIX  64          // spatial size
#define C_MAIN 192       // CIN + 2E
#define C_PROJ 128       // CIN + E
#define CO_MAIN 320      // 5E
#define CO_PROJ 192      // 3E

// ---- warp-MMA GEMM config (main fused conv) ----
#define NCHUNK 54               // 9 taps * 6 channel-blocks of 32
#define ASTR 40                 // padded fp16 row stride
#define TILE_ELEMS (128 * ASTR) // 5120 fp16 per tile
#define TILE_BYTES (TILE_ELEMS * 2)  // 10240 B
#define MMA_SMEM (4 * TILE_BYTES)    // 40960 B (2 bufs x {A,B})

// ---- out-conv MMA config ----
#define OCHUNK 18               // 9 taps * 2 channel-blocks of 32
#define OA_ELEMS (64 * ASTR)    // A tile 64 x ASTR
#define OB_ELEMS (128 * ASTR)   // B tile 128 x ASTR
#define OBUF_ELEMS (OA_ELEMS + OB_ELEMS)
#define OC_SMEM (2 * OBUF_ELEMS * 2)  // 30720 B

#define WPREP_MAIN (2 * 4 * NCHUNK)   // 432 blocks
#define WPREP_OUT  (2 * OCHUNK)       // 36 blocks

// ---------------- scratch (device globals; no allocation) ----------------
__device__ unsigned g_bpk [BB * (C_MAIN / 2) * PIX]; // fp16 channel-pair packed
__device__ float g_gates[BB * CO_MAIN * PIX];   // (B,320,64)
__device__ float g_kqv  [BB * CO_PROJ * PIX];   // (B,192,64)
__device__ float g_attn [BB * EE * PIX];        // (B,64,64)
__device__ float g_ao   [BB * EE * PIX];        // out-conv + residual
__device__ float g_out  [BB * EE * PIX];        // (B,64,64)
__device__ float g_bias [BB * MEM];
__device__ float g_nd   [BB];
__device__ int   g_is_i32;
// fp16 weight tiles: main conv [layer][mtile][chunk][128x32], out conv [layer][chunk][64x32]
__device__ __half g_wA[2 * 4 * NCHUNK * 4096];
__device__ __half g_wO[2 * OCHUNK * 2048];

__device__ __forceinline__ float sigmoidf_(float v) {
    return 1.0f / (1.0f + __expf(-v));
}

__device__ __forceinline__ uint32_t smem_to_u32(const void* p) {
    uint32_t a;
    asm("{ .reg .u64 t; cvta.to.shared.u64 t, %1; cvt.u32.u64 %0, t; }"
        : "=r"(a) : "l"(p));
    return a;
}
__device__ __forceinline__ void ldsm4(uint32_t addr, uint32_t* r) {
    asm volatile("ldmatrix.sync.aligned.m8n8.x4.shared.b16 {%0,%1,%2,%3}, [%4];"
        : "=r"(r[0]), "=r"(r[1]), "=r"(r[2]), "=r"(r[3]) : "r"(addr));
}
__device__ __forceinline__ void mma16816(float* d, const uint32_t* a,
                                         uint32_t b0, uint32_t b1) {
    asm volatile(
        "mma.sync.aligned.m16n8k16.row.col.f32.f16.f16.f32 "
        "{%0,%1,%2,%3}, {%4,%5,%6,%7}, {%8,%9}, {%0,%1,%2,%3};"
        : "+f"(d[0]), "+f"(d[1]), "+f"(d[2]), "+f"(d[3])
        : "r"(a[0]), "r"(a[1]), "r"(a[2]), "r"(a[3]), "r"(b0), "r"(b1));
}
__device__ __forceinline__ void cpasync16(uint32_t dst, const void* src) {
    asm volatile("cp.async.cg.shared.global [%0], [%1], 16;"
                 :: "r"(dst), "l"(src) : "memory");
}
__device__ __forceinline__ void cpasync_commit() {
    asm volatile("cp.async.commit_group;" ::: "memory");
}
__device__ __forceinline__ void cpasync_wait0() {
    asm volatile("cp.async.wait_group 0;" ::: "memory");
}

// ---------------- dtype detection for bool inputs (parallel) ----------------
__global__ void detect_kernel(const int* __restrict__ sm) {
    __shared__ int bad;
    if (threadIdx.x == 0) bad = 0;
    __syncthreads();
    int anybad = 0;
    for (int i = threadIdx.x; i < (BB * MEM) / 4; i += 256) {
        int v = sm[i];
        if (v != 0 && v != 1) anybad = 1;
    }
    if (anybad) bad = 1;
    __syncthreads();
    if (threadIdx.x == 0) g_is_i32 = !bad;
}

__device__ __forceinline__ int read_bool(const void* p, int idx) {
    if (g_is_i32) return ((const int*)p)[idx] != 0;
    return ((const unsigned char*)p)[idx] != 0;
}

// ---------------- bias + notdone ----------------
__global__ void bias_kernel(const void* __restrict__ src_mask,
                            const void* __restrict__ notdone) {
    int t = blockIdx.x * 256 + threadIdx.x;
    if (t < BB) g_nd[t] = read_bool(notdone, t) ? 1.0f : 0.0f;
    if (t >= BB * MEM) return;
    int b = t / MEM, m = t - b * MEM;
    float v;
    if (m == MEM - 1) {
        v = 3.0f;  // MASK_B
    } else {
        bool masked = read_bool(src_mask, b * MEM + m + 1) || !read_bool(notdone, b);
        v = masked ? -1e9f : 0.0f;
    }
    g_bias[t] = v;
}

// ---------------- weight prepass: main + out conv fp16 tiles --------------
__global__ void wprep_kernel(const float* __restrict__ main_w,
                             const float* __restrict__ proj_w,
                             const float* __restrict__ out_w) {
    int id = blockIdx.x;
    if (id < WPREP_MAIN) {
        int n = id / (4 * NCHUNK);
        int r2 = id % (4 * NCHUNK);
        int mtile = r2 / NCHUNK;
        int chunk = r2 % NCHUNK;
        int t  = chunk / 6;
        int c0 = (chunk % 6) * 32;
        __half* dh = g_wA + (size_t)id * 4096;
        for (int e = threadIdx.x; e < 4096; e += 256) {
            int r = e >> 5, kk = e & 31;
            int c = c0 + kk;
            int gco = mtile * 128 + r;
            float w = 0.0f;
            if (gco < CO_MAIN) {
                w = main_w[(((size_t)n * CO_MAIN + gco) * C_MAIN + c) * 9 + t];
            } else if (c < C_PROJ) {
                w = proj_w[(((size_t)n * CO_PROJ + (gco - CO_MAIN)) * C_PROJ + c) * 9 + t];
            }
            dh[e] = __float2half_rn(w);
        }
    } else {
        int id2 = id - WPREP_MAIN;       // out-conv tiles
        int n = id2 / OCHUNK;
        int chunk = id2 % OCHUNK;
        int t  = chunk >> 1;
        int c0 = (chunk & 1) * 32;
        __half* dh = g_wO + (size_t)id2 * 2048;
        for (int e = threadIdx.x; e < 2048; e += 256) {
            int r = e >> 5, kk = e & 31;
            float w = out_w[(((size_t)n * EE + r) * EE + c0 + kk) * 9 + t];
            dh[e] = __float2half_rn(w);
        }
    }
}

// ---------------- build concat input, fp16 channel-pair packed -----------
__global__ void prep_kernel(const float* __restrict__ x,
                            const float* __restrict__ h0,
                            int n, int first) {
    int idx = blockIdx.x * 256 + threadIdx.x;
    if (idx >= BB * (C_MAIN / 2) * PIX) return;
    int b = idx / ((C_MAIN / 2) * PIX);
    int r = idx - b * ((C_MAIN / 2) * PIX);
    int cp = r >> 6;
    int p = r & 63;
    float nd = g_nd[b];
    float vv[2];
#pragma unroll
    for (int s = 0; s < 2; s++) {
        int c = 2 * cp + s;
        float v;
        if (c < CIN) {
            v = x[b * (CIN * PIX) + c * PIX + p];
        } else if (c < CIN + EE) {
            if (first)
                v = h0[((size_t)(LNUM - 1) * BB + b) * (EE * PIX) + (c - CIN) * PIX + p] * nd;
            else
                v = g_out[(size_t)b * (EE * PIX) + (c - CIN) * PIX + p];
        } else {
            v = h0[((size_t)n * BB + b) * (EE * PIX) + (c - CIN - EE) * PIX + p] * nd;
        }
        vv[s] = v;
    }
    __half2 hp = make_half2(__float2half_rn(vv[0]), __float2half_rn(vv[1]));
    g_bpk[idx] = *(unsigned*)&hp;
}

// ---------------- warp-MMA fused conv GEMM (plain fp16) ------------------
__global__ void __launch_bounds__(256, 2)
conv_mma_kernel(const float* __restrict__ main_b,
                const float* __restrict__ proj_b,
                int n) {
    extern __shared__ __half smb[];
    uint32_t smb_u = smem_to_u32(smb);

    int tid = threadIdx.x;
    int lane = tid & 31, w = tid >> 5;
    int ntile = blockIdx.x, mtile = blockIdx.y;
    int b0 = ntile * 2;
    int mrow0 = (w >> 1) * 32;
    int nc0 = (w & 1) * 64;

    float acc[2][8][4];
#pragma unroll
    for (int mi = 0; mi < 2; mi++)
#pragma unroll
        for (int ni = 0; ni < 8; ni++)
#pragma unroll
            for (int j = 0; j < 4; j++) acc[mi][ni][j] = 0.0f;

    int lr = lane & 15, lc = lane >> 4;
    uint32_t aoff = (uint32_t)(((mrow0 + lr) * ASTR + lc * 8) * 2);
    uint32_t boff = (uint32_t)(((nc0 + lr) * ASTR + lc * 8) * 2);

    int brow = tid >> 1, half = tid & 1;
    int bb = brow >> 6, px = brow & 63;
    int yy = px >> 3, xx = px & 7;

    unsigned regB[8];

    auto loadB = [&](int chunk) {
        int t = chunk / 6;
        int cp0 = (chunk % 6) * 16;
        int ty = t / 3, tx = t % 3;
        int iy = yy + ty - 1, ix = xx + tx - 1;
        bool valid = ((unsigned)iy < 8u) && ((unsigned)ix < 8u);
        const unsigned* src = g_bpk
            + ((size_t)(b0 + bb) * (C_MAIN / 2) + cp0 + half * 8) * PIX
            + (valid ? iy * 8 + ix : 0);
#pragma unroll
        for (int j = 0; j < 8; j++)
            regB[j] = valid ? src[j * PIX] : 0u;
    };
    auto issueA = [&](int chunk, int buf) {
        size_t toff = (((size_t)n * 4 + mtile) * NCHUNK + chunk) * 4096;
        const char* gh = (const char*)(g_wA + toff);
        uint32_t base = smb_u + (uint32_t)buf * 2 * TILE_BYTES;
        {
            int e = tid;
            int row = e >> 2, c16 = e & 3;
            cpasync16(base + row * (ASTR * 2) + c16 * 16, gh + e * 16);
            e = tid + 256;
            row = e >> 2; c16 = e & 3;
            cpasync16(base + row * (ASTR * 2) + c16 * 16, gh + e * 16);
        }
        cpasync_commit();
    };
    auto storeB = [&](int buf) {
        __half* base = smb + (size_t)buf * 2 * TILE_ELEMS;
        unsigned* bh = (unsigned*)(base + TILE_ELEMS) + brow * (ASTR / 2) + half * 8;
#pragma unroll
        for (int j = 0; j < 8; j++) bh[j] = regB[j];
    };

    issueA(0, 0);
    loadB(0);
    storeB(0);
    cpasync_wait0();
    __syncthreads();

    for (int chunk = 0; chunk < NCHUNK; chunk++) {
        int buf = chunk & 1;
        if (chunk + 1 < NCHUNK) {
            issueA(chunk + 1, 1 - buf);
            loadB(chunk + 1);
        }

        uint32_t pbase = smb_u + (uint32_t)buf * 2 * TILE_BYTES;
        uint32_t pA = pbase, pB = pbase + TILE_BYTES;
#pragma unroll
        for (int ks = 0; ks < 2; ks++) {
            uint32_t kb = (uint32_t)(ks * 32);
            uint32_t ah[2][4], bh[4][4];
            ldsm4(pA + aoff + kb, ah[0]);
            ldsm4(pA + aoff + 16 * ASTR * 2 + kb, ah[1]);
#pragma unroll
            for (int pn = 0; pn < 4; pn++)
                ldsm4(pB + boff + pn * 16 * ASTR * 2 + kb, bh[pn]);
#pragma unroll
            for (int mi = 0; mi < 2; mi++) {
#pragma unroll
                for (int ni = 0; ni < 8; ni++) {
                    int pn = ni >> 1, o = ni & 1;
                    mma16816(acc[mi][ni], ah[mi], bh[pn][o], bh[pn][o + 2]);
                }
            }
        }
        if (chunk + 1 < NCHUNK) {
            storeB(1 - buf);
            cpasync_wait0();
            __syncthreads();
        }
    }

    int batch = b0 + (w & 1);
#pragma unroll
    for (int mi = 0; mi < 2; mi++) {
#pragma unroll
        for (int rr = 0; rr < 2; rr++) {
            int r = mrow0 + mi * 16 + rr * 8 + (lane >> 2);
            int gr = mtile * 128 + r;
            bool ismain = (gr < CO_MAIN);
            float bias = ismain ? main_b[n * CO_MAIN + gr]
                                : proj_b[n * CO_PROJ + (gr - CO_MAIN)];
            float* dst = ismain
                ? g_gates + ((size_t)batch * CO_MAIN + gr) * PIX
                : g_kqv  + ((size_t)batch * CO_PROJ + (gr - CO_MAIN)) * PIX;
#pragma unroll
            for (int ni = 0; ni < 8; ni++) {
                int pxc = ni * 8 + (lane & 3) * 2;
                float2 v;
                v.x = acc[mi][ni][rr * 2 + 0] + bias;
                v.y = acc[mi][ni][rr * 2 + 1] + bias;
                *(float2*)&dst[pxc] = v;
            }
        }
    }
}

// ---------------- attention over rolling memory (mask-skipped) -----------
__global__ void attn_kernel(const float* __restrict__ k0,
                            const float* __restrict__ v0,
                            const float* __restrict__ pos_w,
                            const float* __restrict__ pos_b,
                            int n) {
    int b = blockIdx.x;
    int h = blockIdx.y;
    int tid = threadIdx.x;
    __shared__ float q[THD], kn[THD], vn[THD];
    __shared__ float sc[MEM], wts[MEM];
    __shared__ int act[MEM];
    __shared__ int nact;

    const float* kqv = g_kqv + (size_t)b * CO_PROJ * PIX;
    const float rscale = 0.044194173824159216f;  // 1/sqrt(512)
    for (int d = tid; d < THD; d += 256) {
        int hd = d >> 6, hw = d & 63;
        kn[d] = kqv[(h * 24 + hd) * PIX + hw];
        q[d]  = kqv[(h * 24 + 8 + hd) * PIX + hw] * rscale;
        vn[d] = kqv[(h * 24 + 16 + hd) * PIX + hw];
    }
    __syncthreads();

    const float* kb  = k0 + ((((size_t)n * BB + b) * NHH + h) * MEM) * THD;
    const float* pwb = pos_w + (size_t)n * MEM * (NHH * THD) + h * THD;
    int warp = tid >> 5, lane = tid & 31;
    for (int m = warp; m < MEM; m += 8) {
        float bm = g_bias[b * MEM + m];
        if (bm < -1e8f) {
            // masked slot: exp underflows to exact 0; skip the 2KB k-row
            if (lane == 0) sc[m] = -1e9f;
            continue;
        }
        const float* kr = (m < MEM - 1) ? (kb + (size_t)(m + 1) * THD) : kn;
        const float* pr = pwb + (size_t)m * (NHH * THD);
        float p = 0.0f;
        for (int d = lane; d < THD; d += 32)
            p = fmaf(q[d], kr[d] + pr[d], p);
#pragma unroll
        for (int o = 16; o; o >>= 1) p += __shfl_xor_sync(0xffffffffu, p, o);
        if (lane == 0)
            sc[m] = p + bm + pos_b[(size_t)n * MEM * NHH + m * NHH + h];
    }
    __syncthreads();
    if (tid == 0) {
        float mx = sc[0];
#pragma unroll
        for (int m = 1; m < MEM; m++) mx = fmaxf(mx, sc[m]);
        float s = 0.0f;
#pragma unroll
        for (int m = 0; m < MEM; m++) {
            float e = __expf(sc[m] - mx);
            wts[m] = e;
            s += e;
        }
        float inv = 1.0f / s;
        int na = 0;
#pragma unroll
        for (int m = 0; m < MEM; m++) {
            wts[m] *= inv;
            if (m < MEM - 1 && wts[m] != 0.0f) act[na++] = m;
        }
        nact = na;
    }
    __syncthreads();

    const float* vb = v0 + ((((size_t)n * BB + b) * NHH + h) * MEM) * THD;
    int na = nact;
    for (int d = tid; d < THD; d += 256) {
        float acc = wts[MEM - 1] * vn[d];
        for (int i = 0; i < na; i++) {
            int m = act[i];
            acc = fmaf(wts[m], vb[(size_t)(m + 1) * THD + d], acc);
        }
        int hd = d >> 6, hw = d & 63;
        g_attn[(size_t)b * (EE * PIX) + (h * 8 + hd) * PIX + hw] = acc;
    }
}

// ---------------- out conv via fp16 MMA (+bias +residual) ----------------
__global__ void __launch_bounds__(256, 2)
outconv_mma_kernel(const float* __restrict__ out_b,
                   const float* __restrict__ x,
                   int n) {
    extern __shared__ __half smb[];
    uint32_t smb_u = smem_to_u32(smb);

    int tid = threadIdx.x;
    int lane = tid & 31, w = tid >> 5;
    int b0 = blockIdx.x * 2;
    int mrow0 = (w >> 1) * 16;
    int nc0 = (w & 1) * 64;

    float acc[8][4];
#pragma unroll
    for (int ni = 0; ni < 8; ni++)
#pragma unroll
        for (int j = 0; j < 4; j++) acc[ni][j] = 0.0f;

    int lr = lane & 15, lc = lane >> 4;
    uint32_t aoff = (uint32_t)(((mrow0 + lr) * ASTR + lc * 8) * 2);
    uint32_t boff = (uint32_t)(((nc0 + lr) * ASTR + lc * 8) * 2);

    int brow = tid >> 1, half = tid & 1;
    int bb = brow >> 6, px = brow & 63;
    int yy = px >> 3, xx = px & 7;

    unsigned regB[8];

    auto loadB = [&](int chunk) {
        int t = chunk >> 1;
        int c0 = (chunk & 1) * 32 + half * 16;
        int ty = t / 3, tx = t % 3;
        int iy = yy + ty - 1, ix = xx + tx - 1;
        bool valid = ((unsigned)iy < 8u) && ((unsigned)ix < 8u);
        const float* src = g_attn + ((size_t)(b0 + bb) * EE + c0) * PIX
                                  + (valid ? iy * 8 + ix : 0);
#pragma unroll
        for (int j = 0; j < 8; j++) {
            float v0 = valid ? src[(2 * j) * PIX] : 0.0f;
            float v1 = valid ? src[(2 * j + 1) * PIX] : 0.0f;
            __half2 hp = make_half2(__float2half_rn(v0), __float2half_rn(v1));
            regB[j] = *(unsigned*)&hp;
        }
    };
    auto issueA = [&](int chunk, int buf) {
        size_t toff = ((size_t)n * OCHUNK + chunk) * 2048;
        const char* gh = (const char*)(g_wO + toff);
        uint32_t base = smb_u + (uint32_t)buf * OBUF_ELEMS * 2;
        int e = tid;
        int row = e >> 2, c16 = e & 3;
        cpasync16(base + row * (ASTR * 2) + c16 * 16, gh + e * 16);
        cpasync_commit();
    };
    auto storeB = [&](int buf) {
        __half* base = smb + (size_t)buf * OBUF_ELEMS + OA_ELEMS;
        unsigned* bh = (unsigned*)base + brow * (ASTR / 2) + half * 8;
#pragma unroll
        for (int j = 0; j < 8; j++) bh[j] = regB[j];
    };

    issueA(0, 0);
    loadB(0);
    storeB(0);
    cpasync_wait0();
    __syncthreads();

    for (int chunk = 0; chunk < OCHUNK; chunk++) {
        int buf = chunk & 1;
        if (chunk + 1 < OCHUNK) {
            issueA(chunk + 1, 1 - buf);
            loadB(chunk + 1);
        }

        uint32_t pbase = smb_u + (uint32_t)buf * OBUF_ELEMS * 2;
        uint32_t pA = pbase, pB = pbase + OA_ELEMS * 2;
#pragma unroll
        for (int ks = 0; ks < 2; ks++) {
            uint32_t kb = (uint32_t)(ks * 32);
            uint32_t ah[4], bh[4][4];
            ldsm4(pA + aoff + kb, ah);
#pragma unroll
            for (int pn = 0; pn < 4; pn++)
                ldsm4(pB + boff + pn * 16 * ASTR * 2 + kb, bh[pn]);
#pragma unroll
            for (int ni = 0; ni < 8; ni++) {
                int pn = ni >> 1, o = ni & 1;
                mma16816(acc[ni], ah, bh[pn][o], bh[pn][o + 2]);
            }
        }
        if (chunk + 1 < OCHUNK) {
            storeB(1 - buf);
            cpasync_wait0();
            __syncthreads();
        }
    }

    int batch = b0 + (w & 1);
    const float* xr = x + (size_t)batch * EE * PIX;
    float* aob = g_ao + (size_t)batch * EE * PIX;
#pragma unroll
    for (int rr = 0; rr < 2; rr++) {
        int co = mrow0 + rr * 8 + (lane >> 2);
        float bias = out_b[n * EE + co];
#pragma unroll
        for (int ni = 0; ni < 8; ni++) {
            int pxc = ni * 8 + (lane & 3) * 2;
            float2 rx = *(const float2*)&xr[co * PIX + pxc];
            float2 v;
            v.x = acc[ni][rr * 2 + 0] + bias + rx.x;
            v.y = acc[ni][rr * 2 + 1] + bias + rx.y;
            *(float2*)&aob[co * PIX + pxc] = v;
        }
    }
}

// ---------------- layernorm + LSTM combine ----------------
__global__ void final_ln_kernel(const float* __restrict__ ln_w,
                                const float* __restrict__ ln_b,
                                const float* __restrict__ c0,
                                int n, float* __restrict__ dst_last, int last) {
    __shared__ float red[16];
    __shared__ float s_mu, s_rv;
    int b = blockIdx.x;
    int tid = threadIdx.x;

    const float* aop = g_ao + (size_t)b * EE * PIX;
    float v16[16];
    float s1 = 0.0f, s2 = 0.0f;
#pragma unroll
    for (int j = 0; j < 16; j++) {
        float v = aop[tid + 256 * j];
        v16[j] = v;
        s1 += v;
        s2 += v * v;
    }
    int warp = tid >> 5, lane = tid & 31;
#pragma unroll
    for (int o = 16; o; o >>= 1) {
        s1 += __shfl_xor_sync(0xffffffffu, s1, o);
        s2 += __shfl_xor_sync(0xffffffffu, s2, o);
    }
    if (lane == 0) { red[warp] = s1; red[8 + warp] = s2; }
    __syncthreads();
    if (tid == 0) {
        float a = 0.0f, q2 = 0.0f;
#pragma unroll
        for (int w2 = 0; w2 < 8; w2++) { a += red[w2]; q2 += red[8 + w2]; }
        float mu = a * (1.0f / 4096.0f);
        float var = q2 * (1.0f / 4096.0f) - mu * mu;
        s_mu = mu;
        s_rv = rsqrtf(var + 1e-5f);
    }
    __syncthreads();
    float mu = s_mu, rv = s_rv;

    const float* gb = g_gates + (size_t)b * CO_MAIN * PIX;
    const float* cb = c0 + ((size_t)n * BB + b) * (EE * PIX);
    float nd = g_nd[b];
    float* dst = (last ? dst_last : g_out) + (size_t)b * EE * PIX;
    const float* lw = ln_w + (size_t)n * EE * PIX;
    const float* lb = ln_b + (size_t)n * EE * PIX;
#pragma unroll
    for (int j = 0; j < 16; j++) {
        int i = tid + 256 * j;
        int c = i >> 6, p = i & 63;
        float aon = (v16[j] - mu) * rv * lw[i] + lb[i];
        float gi = sigmoidf_(gb[(0 * EE + c) * PIX + p]);
        float gf = sigmoidf_(gb[(1 * EE + c) * PIX + p]);
        float go = sigmoidf_(gb[(2 * EE + c) * PIX + p]);
        float gg = tanhf(gb[(3 * EE + c) * PIX + p]);
        float ga = sigmoidf_(gb[(4 * EE + c) * PIX + p]);
        float cn = gf * (cb[i] * nd) + gi * gg + ga * tanhf(aon);
        dst[i] = go * tanhf(cn);
    }
}

// ---------------- launch ----------------
extern "C" void kernel_launch(void* const* d_in, const int* in_sizes, int n_in,
                              void* d_out, int out_size) {
    const float* x       = (const float*)d_in[0];
    const float* h0      = (const float*)d_in[1];
    const float* c0      = (const float*)d_in[2];
    const float* k0      = (const float*)d_in[3];
    const float* v0      = (const float*)d_in[4];
    const void*  src_mask = d_in[5];
    const void*  notdone  = d_in[6];
    const float* main_w  = (const float*)d_in[7];
    const float* main_b  = (const float*)d_in[8];
    const float* proj_w  = (const float*)d_in[9];
    const float* proj_b  = (const float*)d_in[10];
    const float* out_w   = (const float*)d_in[11];
    const float* out_b   = (const float*)d_in[12];
    const float* ln_w    = (const float*)d_in[13];
    const float* ln_b    = (const float*)d_in[14];
    const float* pos_w   = (const float*)d_in[15];
    const float* pos_b   = (const float*)d_in[16];
    float* out = (float*)d_out;

    cudaFuncSetAttribute(conv_mma_kernel,
                         cudaFuncAttributeMaxDynamicSharedMemorySize, MMA_SMEM);
    cudaFuncSetAttribute(outconv_mma_kernel,
                         cudaFuncAttributeMaxDynamicSharedMemorySize, OC_SMEM);

    detect_kernel<<<1, 256>>>((const int*)src_mask);
    bias_kernel<<<(BB * MEM + 255) / 256, 256>>>(src_mask, notdone);
    wprep_kernel<<<WPREP_MAIN + WPREP_OUT, 256>>>(main_w, proj_w, out_w);
    for (int n = 0; n < LNUM; n++) {
        int tot = BB * (C_MAIN / 2) * PIX;
        prep_kernel<<<(tot + 255) / 256, 256>>>(x, h0, n, n == 0 ? 1 : 0);
        conv_mma_kernel<<<dim3(64, 4), 256, MMA_SMEM>>>(main_b, proj_b, n);
        attn_kernel<<<dim3(BB, NHH), 256>>>(k0, v0, pos_w, pos_b, n);
        outconv_mma_kernel<<<64, 256, OC_SMEM>>>(out_b, x, n);
        final_ln_kernel<<<BB, 256>>>(ln_w, ln_b, c0, n,
                                     out, n == LNUM - 1 ? 1 : 0);
    }
}